// round 1
// baseline (speedup 1.0000x reference)
#include <cuda_runtime.h>
#include <math.h>

#define TT 8192
#define HH 2048
#define NCHUNK 64
#define CLEN 128

// ---- scratch (device globals: allocation-free) ----
__device__ float g_k[TT * HH];
__device__ float g_v[TT * HH];
__device__ float g_r[TT * HH];   // r, then overwritten with r*wkv in phase C
__device__ float g_Sa[NCHUNK * HH];
__device__ float g_Sb[NCHUNK * HH];
__device__ float g_Sm[NCHUNK * HH];
__device__ float g_Pa[NCHUNK * HH];
__device__ float g_Pb[NCHUNK * HH];
__device__ float g_Pp[NCHUNK * HH];

// ================= GEMM: C[M,N] = act(A'[M,K] @ W[K,N]) (+hidden) =================
// MODE 0: A' = token-shift mix of hidden (key/value path), no activation
// MODE 1: same A' mix, sigmoid activation (receptance)
// MODE 2: A' = A as-is (r*wkv), epilogue adds hidden
#define BM 128
#define BN 128
#define BK 16

template <int MODE>
__device__ __forceinline__ void load_tiles(
    const float* __restrict__ A, const float* __restrict__ sx,
    const float* __restrict__ mixv, const float* __restrict__ W,
    int row0, int col0, int kt, int tid, float4* aR, float4* bR)
{
#pragma unroll
    for (int i = 0; i < 2; ++i) {
        int v = tid + i * 256;
        int m = v >> 2;
        int kq = (v & 3) << 2;
        int t = row0 + m;
        int gk = kt + kq;
        int off = t * HH + gk;
        float4 hv = *reinterpret_cast<const float4*>(A + off);
        if (MODE == 2) {
            aR[i] = hv;
        } else {
            float4 pv = (t > 0) ? *reinterpret_cast<const float4*>(A + off - HH)
                                : *reinterpret_cast<const float4*>(sx + gk);
            float4 mv = *reinterpret_cast<const float4*>(mixv + gk);
            aR[i].x = fmaf(hv.x - pv.x, mv.x, pv.x);
            aR[i].y = fmaf(hv.y - pv.y, mv.y, pv.y);
            aR[i].z = fmaf(hv.z - pv.z, mv.z, pv.z);
            aR[i].w = fmaf(hv.w - pv.w, mv.w, pv.w);
        }
    }
#pragma unroll
    for (int i = 0; i < 2; ++i) {
        int u = tid + i * 256;
        int kq = u >> 5;
        int n = (u & 31) << 2;
        bR[i] = *reinterpret_cast<const float4*>(W + (kt + kq) * HH + col0 + n);
    }
}

template <int MODE>
__global__ void __launch_bounds__(256)
gemm_kernel(const float* __restrict__ A, const float* __restrict__ sx,
            const float* __restrict__ mixv, const float* __restrict__ W,
            const float* __restrict__ addv, float* __restrict__ out)
{
    __shared__ float As[BK][BM + 4];
    __shared__ float Bs[BK][BN];
    const int tid = threadIdx.x;
    const int row0 = blockIdx.y * BM;
    const int col0 = blockIdx.x * BN;
    const int tx = tid & 15;
    const int ty = tid >> 4;

    float4 aR[2], bR[2];
    load_tiles<MODE>(A, sx, mixv, W, row0, col0, 0, tid, aR, bR);

    float acc[8][8];
#pragma unroll
    for (int i = 0; i < 8; ++i)
#pragma unroll
        for (int j = 0; j < 8; ++j) acc[i][j] = 0.f;

    for (int kt = 0; kt < HH; kt += BK) {
        __syncthreads();
#pragma unroll
        for (int i = 0; i < 2; ++i) {
            int v = tid + i * 256;
            int m = v >> 2;
            int kq = (v & 3) << 2;
            As[kq + 0][m] = aR[i].x;
            As[kq + 1][m] = aR[i].y;
            As[kq + 2][m] = aR[i].z;
            As[kq + 3][m] = aR[i].w;
            int bk = v >> 5;
            int n = (v & 31) << 2;
            *reinterpret_cast<float4*>(&Bs[bk][n]) = bR[i];
        }
        __syncthreads();
        if (kt + BK < HH)
            load_tiles<MODE>(A, sx, mixv, W, row0, col0, kt + BK, tid, aR, bR);

#pragma unroll
        for (int kk = 0; kk < BK; ++kk) {
            float a[8], b[8];
            *reinterpret_cast<float4*>(&a[0]) = *reinterpret_cast<const float4*>(&As[kk][ty * 8]);
            *reinterpret_cast<float4*>(&a[4]) = *reinterpret_cast<const float4*>(&As[kk][ty * 8 + 4]);
            *reinterpret_cast<float4*>(&b[0]) = *reinterpret_cast<const float4*>(&Bs[kk][tx * 8]);
            *reinterpret_cast<float4*>(&b[4]) = *reinterpret_cast<const float4*>(&Bs[kk][tx * 8 + 4]);
#pragma unroll
            for (int i = 0; i < 8; ++i)
#pragma unroll
                for (int j = 0; j < 8; ++j)
                    acc[i][j] = fmaf(a[i], b[j], acc[i][j]);
        }
    }

#pragma unroll
    for (int i = 0; i < 8; ++i) {
        int r = row0 + ty * 8 + i;
#pragma unroll
        for (int j4 = 0; j4 < 8; j4 += 4) {
            int cidx = col0 + tx * 8 + j4;
            float4 v;
            v.x = acc[i][j4 + 0];
            v.y = acc[i][j4 + 1];
            v.z = acc[i][j4 + 2];
            v.w = acc[i][j4 + 3];
            if (MODE == 1) {
                v.x = 1.f / (1.f + __expf(-v.x));
                v.y = 1.f / (1.f + __expf(-v.y));
                v.z = 1.f / (1.f + __expf(-v.z));
                v.w = 1.f / (1.f + __expf(-v.w));
            }
            if (MODE == 2) {
                float4 hv = *reinterpret_cast<const float4*>(addv + r * HH + cidx);
                v.x += hv.x; v.y += hv.y; v.z += hv.z; v.w += hv.w;
            }
            *reinterpret_cast<float4*>(out + r * HH + cidx) = v;
        }
    }
}

// ================= WKV chunked scan =================
// Phase A: per-chunk local summaries from empty state.
__global__ void scan_phaseA(const float* __restrict__ td)
{
    int h = blockIdx.x * blockDim.x + threadIdx.x;
    int c = blockIdx.y;
    float w = -expf(td[h]);
    float a = 0.f, b = 0.f, p = -1e30f;
    int t0 = c * CLEN;
    for (int t = t0; t < t0 + CLEN; ++t) {
        int idx = t * HH + h;
        float kk = g_k[idx], vv = g_v[idx];
        float ww = w + p;
        float q = fmaxf(ww, kk);
        float e1 = __expf(ww - q);
        float e2 = __expf(kk - q);
        a = e1 * a + e2 * vv;
        b = e1 * b + e2;
        p = q;
    }
    g_Sa[c * HH + h] = a;
    g_Sb[c * HH + h] = b;
    g_Sm[c * HH + h] = p;
}

// Phase B: sequential combine across chunk summaries; records exclusive prefix
// per chunk; writes final-state + last-hidden-row outputs.
__global__ void scan_phaseB(const float* __restrict__ td,
                            const float* __restrict__ aa0, const float* __restrict__ bb0,
                            const float* __restrict__ pp0, const float* __restrict__ hidden,
                            float* __restrict__ out)
{
    int h = blockIdx.x * blockDim.x + threadIdx.x;
    float w = -expf(td[h]);
    float wL = w * (float)CLEN;
    float a = aa0[h], b = bb0[h], p = pp0[h];
    for (int c = 0; c < NCHUNK; ++c) {
        g_Pa[c * HH + h] = a;
        g_Pb[c * HH + h] = b;
        g_Pp[c * HH + h] = p;
        float m = g_Sm[c * HH + h];
        float pd = p + wL;
        float q = fmaxf(pd, m);
        float e1 = __expf(pd - q);
        float e2 = __expf(m - q);
        a = e1 * a + e2 * g_Sa[c * HH + h];
        b = e1 * b + e2 * g_Sb[c * HH + h];
        p = q;
    }
    out[TT * HH + h] = hidden[(TT - 1) * HH + h];
    out[TT * HH + HH + h] = a;
    out[TT * HH + 2 * HH + h] = b;
    out[TT * HH + 3 * HH + h] = p;
}

// Phase C: replay each chunk from its true prefix, emit r*wkv in-place over g_r.
__global__ void scan_phaseC(const float* __restrict__ td, const float* __restrict__ tf)
{
    int h = blockIdx.x * blockDim.x + threadIdx.x;
    int c = blockIdx.y;
    float w = -expf(td[h]);
    float u = tf[h];
    float a = g_Pa[c * HH + h], b = g_Pb[c * HH + h], p = g_Pp[c * HH + h];
    int t0 = c * CLEN;
    for (int t = t0; t < t0 + CLEN; ++t) {
        int idx = t * HH + h;
        float kk = g_k[idx], vv = g_v[idx];
        // output with bonus (state before update)
        float ww = u + kk;
        float q = fmaxf(p, ww);
        float e1 = __expf(p - q);
        float e2 = __expf(ww - q);
        float wkv = (e1 * a + e2 * vv) / (e1 * b + e2);
        g_r[idx] = g_r[idx] * wkv;
        // state update with decay
        float ww2 = w + p;
        float q2 = fmaxf(ww2, kk);
        float f1 = __expf(ww2 - q2);
        float f2 = __expf(kk - q2);
        a = f1 * a + f2 * vv;
        b = f1 * b + f2;
        p = q2;
    }
}

extern "C" void kernel_launch(void* const* d_in, const int* in_sizes, int n_in,
                              void* d_out, int out_size)
{
    const float* hidden = (const float*)d_in[0];
    const float* sx     = (const float*)d_in[1];
    const float* aa     = (const float*)d_in[2];
    const float* bb     = (const float*)d_in[3];
    const float* pp     = (const float*)d_in[4];
    const float* td     = (const float*)d_in[5];
    const float* tf     = (const float*)d_in[6];
    const float* tmk    = (const float*)d_in[7];
    const float* tmv    = (const float*)d_in[8];
    const float* tmr    = (const float*)d_in[9];
    const float* Wk     = (const float*)d_in[10];
    const float* Wv     = (const float*)d_in[11];
    const float* Wr     = (const float*)d_in[12];
    const float* Wo     = (const float*)d_in[13];
    float* out = (float*)d_out;

    float *pk, *pv, *pr;
    cudaGetSymbolAddress((void**)&pk, g_k);
    cudaGetSymbolAddress((void**)&pv, g_v);
    cudaGetSymbolAddress((void**)&pr, g_r);

    dim3 grid(HH / BN, TT / BM);
    gemm_kernel<0><<<grid, 256>>>(hidden, sx, tmk, Wk, nullptr, pk);
    gemm_kernel<0><<<grid, 256>>>(hidden, sx, tmv, Wv, nullptr, pv);
    gemm_kernel<1><<<grid, 256>>>(hidden, sx, tmr, Wr, nullptr, pr);

    dim3 sgrid(HH / 256, NCHUNK);
    scan_phaseA<<<sgrid, 256>>>(td);
    scan_phaseB<<<HH / 256, 256>>>(td, aa, bb, pp, hidden, out);
    scan_phaseC<<<sgrid, 256>>>(td, tf);

    gemm_kernel<2><<<grid, 256>>>(pr, nullptr, nullptr, Wo, hidden, out);
}

// round 4
// speedup vs baseline: 2.2315x; 2.2315x over previous
#include <cuda_runtime.h>
#include <cuda_bf16.h>
#include <math.h>
#include <cstdint>

#define TT 8192
#define HH 2048
#define NCHUNK 64
#define CLEN 128

// GEMM tiling
#define BM 128
#define BN 128
#define BKE 32               // K elements per stage (bf16)
#define LDA 40               // row stride in elements (pad 8 -> 80B, conflict-free ldmatrix)
#define TILE_ELEMS (128 * LDA)
#define STAGE_BYTES (2 * TILE_ELEMS * 2)   // A tile + B tile, bf16
#define NSTAGE 4
#define GSMEM (NSTAGE * STAGE_BYTES)       // 81920
#define KITER (3 * HH / BKE)               // 192 (3 split phases x 64)

// ---------------- scratch (device globals; allocation-free) ----------------
__device__ float g_k[TT * HH];
__device__ float g_v[TT * HH];
__device__ float g_r[TT * HH];
__device__ __nv_bfloat16 g_axh[3][TT * HH];  // mixed activations hi (k,v,r)
__device__ __nv_bfloat16 g_axl[3][TT * HH];  // lo
__device__ __nv_bfloat16 g_wh[4][HH * HH];   // W^T hi (k,v,r,o)
__device__ __nv_bfloat16 g_wl[4][HH * HH];   // lo
__device__ __nv_bfloat16 g_rwh[TT * HH];     // r*wkv hi
__device__ __nv_bfloat16 g_rwl[TT * HH];     // lo
__device__ float g_Sa[NCHUNK * HH];
__device__ float g_Sb[NCHUNK * HH];
__device__ float g_Sm[NCHUNK * HH];
__device__ float g_Pa[NCHUNK * HH];
__device__ float g_Pb[NCHUNK * HH];
__device__ float g_Pp[NCHUNK * HH];

// ---------------- PTX helpers (plain sm_80-era: work on sm_103 target) ----------------
__device__ __forceinline__ uint32_t smem_u32(const void* p) {
    uint32_t a;
    asm("{ .reg .u64 t; cvta.to.shared.u64 t, %1; cvt.u32.u64 %0, t; }" : "=r"(a) : "l"(p));
    return a;
}

#define CP_ASYNC16(dst, src) \
    asm volatile("cp.async.cg.shared.global [%0], [%1], 16;" :: "r"(dst), "l"(src))
#define CP_COMMIT() asm volatile("cp.async.commit_group;" ::: "memory")
#define CP_WAIT2() asm volatile("cp.async.wait_group 2;" ::: "memory")
#define CP_WAIT0() asm volatile("cp.async.wait_group 0;" ::: "memory")

__device__ __forceinline__ void ldmx4(uint32_t* r, uint32_t addr) {
    asm volatile("ldmatrix.sync.aligned.m8n8.x4.shared.b16 {%0,%1,%2,%3}, [%4];"
                 : "=r"(r[0]), "=r"(r[1]), "=r"(r[2]), "=r"(r[3]) : "r"(addr));
}

__device__ __forceinline__ void mma16816(float* d, const uint32_t* a, uint32_t b0, uint32_t b1) {
    asm volatile("mma.sync.aligned.m16n8k16.row.col.f32.bf16.bf16.f32 "
                 "{%0,%1,%2,%3}, {%4,%5,%6,%7}, {%8,%9}, {%0,%1,%2,%3};"
                 : "+f"(d[0]), "+f"(d[1]), "+f"(d[2]), "+f"(d[3])
                 : "r"(a[0]), "r"(a[1]), "r"(a[2]), "r"(a[3]), "r"(b0), "r"(b1));
}

__device__ __forceinline__ void split1(float x, __nv_bfloat16& h, __nv_bfloat16& l) {
    h = __float2bfloat16(x);
    l = __float2bfloat16(x - __bfloat162float(h));
}

// ================= bf16-split mma.sync GEMM =================
// out[M,N](f32) = act( A[M,K] @ B[N,K]^T ), A/B given as hi/lo bf16 pairs.
// 3 accumulation phases over one K-loop: Ahi*Bhi, Alo*Bhi, Ahi*Blo.
// MODE 0: none; MODE 1: sigmoid; MODE 2: + addv
template <int MODE>
__global__ void __launch_bounds__(256, 1)
mmagemm(const __nv_bfloat16* __restrict__ Ahi, const __nv_bfloat16* __restrict__ Alo,
        const __nv_bfloat16* __restrict__ Bhi, const __nv_bfloat16* __restrict__ Blo,
        const float* __restrict__ addv, float* __restrict__ out)
{
    extern __shared__ __nv_bfloat16 sm[];
    const uint32_t sbase = smem_u32(sm);
    const int tid = threadIdx.x;
    const int wid = tid >> 5, lid = tid & 31;
    const int row0 = blockIdx.y * BM;
    const int col0 = blockIdx.x * BN;
    const int wm = (wid >> 1) * 32;   // warp M offset
    const int wn = (wid & 1) * 64;    // warp N offset

    // per-thread cp.async coordinates: 512 16B-chunks per tile, 2 per thread per tile
    const int r0c = tid >> 2;            // rows tid/4 and tid/4+64
    const int c16 = tid & 3;             // 16B chunk within row (8 elements)

    // ldmatrix lane addressing
    const int lrow = lid & 15;
    const int khalf = (lid >> 4) * 8;

    float acc[2][8][4];
#pragma unroll
    for (int mi = 0; mi < 2; ++mi)
#pragma unroll
        for (int ni = 0; ni < 8; ++ni)
#pragma unroll
            for (int j = 0; j < 4; ++j) acc[mi][ni][j] = 0.f;

    auto load_stage = [&](int buf, int it) {
        const int phase = it >> 6;            // 0,1,2
        const int kt = (it & 63) * BKE;
        const __nv_bfloat16* As = (phase == 1) ? Alo : Ahi;
        const __nv_bfloat16* Bs = (phase == 2) ? Blo : Bhi;
        const uint32_t sA = sbase + buf * STAGE_BYTES;
        const uint32_t sB = sA + TILE_ELEMS * 2;
#pragma unroll
        for (int i = 0; i < 2; ++i) {
            const int r = r0c + i * 64;
            const uint32_t so = (r * LDA + c16 * 8) * 2;
            CP_ASYNC16(sA + so, As + (size_t)(row0 + r) * HH + kt + c16 * 8);
            CP_ASYNC16(sB + so, Bs + (size_t)(col0 + r) * HH + kt + c16 * 8);
        }
        CP_COMMIT();
    };

    load_stage(0, 0);
    load_stage(1, 1);
    load_stage(2, 2);

    for (int it = 0; it < KITER; ++it) {
        CP_WAIT2();
        __syncthreads();
        if (it + 3 < KITER) load_stage((it + 3) & 3, it + 3);

        const uint32_t sA = sbase + (it & 3) * STAGE_BYTES;
        const uint32_t sB = sA + TILE_ELEMS * 2;
#pragma unroll
        for (int k16 = 0; k16 < 2; ++k16) {
            uint32_t a[2][4], b[4][4];
#pragma unroll
            for (int mi = 0; mi < 2; ++mi)
                ldmx4(a[mi], sA + ((wm + 16 * mi + lrow) * LDA + k16 * 16 + khalf) * 2);
#pragma unroll
            for (int nt = 0; nt < 4; ++nt)
                ldmx4(b[nt], sB + ((wn + 16 * nt + lrow) * LDA + k16 * 16 + khalf) * 2);
#pragma unroll
            for (int mi = 0; mi < 2; ++mi)
#pragma unroll
                for (int nt = 0; nt < 4; ++nt) {
                    mma16816(acc[mi][2 * nt + 0], a[mi], b[nt][0], b[nt][2]);
                    mma16816(acc[mi][2 * nt + 1], a[mi], b[nt][1], b[nt][3]);
                }
        }
    }
    CP_WAIT0();

    // epilogue: direct fp32 stores from accumulator fragments
    const int erow = wm + (lid >> 2);
    const int ecol = wn + (lid & 3) * 2;
#pragma unroll
    for (int mi = 0; mi < 2; ++mi)
#pragma unroll
        for (int ni = 0; ni < 8; ++ni)
#pragma unroll
            for (int h = 0; h < 2; ++h) {
                const int r = row0 + erow + mi * 16 + h * 8;
                const int c = col0 + ecol + ni * 8;
                float2 v;
                v.x = acc[mi][ni][h * 2 + 0];
                v.y = acc[mi][ni][h * 2 + 1];
                if (MODE == 1) {
                    v.x = 1.f / (1.f + __expf(-v.x));
                    v.y = 1.f / (1.f + __expf(-v.y));
                }
                const size_t o = (size_t)r * HH + c;
                if (MODE == 2) {
                    float2 hv = *reinterpret_cast<const float2*>(addv + o);
                    v.x += hv.x; v.y += hv.y;
                }
                *reinterpret_cast<float2*>(out + o) = v;
            }
}

// ================= split / transpose prep =================
__global__ void __launch_bounds__(256)
split_acts(const float* __restrict__ hidden, const float* __restrict__ sx,
           const float* __restrict__ tmk, const float* __restrict__ tmv,
           const float* __restrict__ tmr)
{
    const int idx = blockIdx.x * 256 + threadIdx.x;  // float4 index
    const int h4 = idx & (HH / 4 - 1);
    float4 hv = reinterpret_cast<const float4*>(hidden)[idx];
    float4 pv = (idx >= HH / 4) ? reinterpret_cast<const float4*>(hidden)[idx - HH / 4]
                                : reinterpret_cast<const float4*>(sx)[h4];
    const float* tms[3] = {tmk, tmv, tmr};
#pragma unroll
    for (int p = 0; p < 3; ++p) {
        float4 mv = reinterpret_cast<const float4*>(tms[p])[h4];
        union { __nv_bfloat16 b[4]; uint2 u; } Hh, Ll;
        float x;
        x = fmaf(hv.x - pv.x, mv.x, pv.x); split1(x, Hh.b[0], Ll.b[0]);
        x = fmaf(hv.y - pv.y, mv.y, pv.y); split1(x, Hh.b[1], Ll.b[1]);
        x = fmaf(hv.z - pv.z, mv.z, pv.z); split1(x, Hh.b[2], Ll.b[2]);
        x = fmaf(hv.w - pv.w, mv.w, pv.w); split1(x, Hh.b[3], Ll.b[3]);
        *reinterpret_cast<uint2*>(&g_axh[p][(size_t)idx * 4]) = Hh.u;
        *reinterpret_cast<uint2*>(&g_axl[p][(size_t)idx * 4]) = Ll.u;
    }
}

// W[K,N] -> W^T[N,K] bf16 hi/lo
__global__ void __launch_bounds__(256)
wsplit(const float* __restrict__ W, __nv_bfloat16* __restrict__ Th, __nv_bfloat16* __restrict__ Tl)
{
    __shared__ float ts[32][33];
    const int n0 = blockIdx.x * 32, k0 = blockIdx.y * 32;
    const int tx = threadIdx.x, ty = threadIdx.y;  // 32 x 8
#pragma unroll
    for (int i = 0; i < 4; ++i)
        ts[ty + i * 8][tx] = W[(size_t)(k0 + ty + i * 8) * HH + n0 + tx];
    __syncthreads();
#pragma unroll
    for (int i = 0; i < 4; ++i) {
        float x = ts[tx][ty + i * 8];
        __nv_bfloat16 h, l;
        split1(x, h, l);
        const size_t o = (size_t)(n0 + ty + i * 8) * HH + k0 + tx;
        Th[o] = h; Tl[o] = l;
    }
}

// ================= WKV chunked scan =================
__global__ void scan_phaseA(const float* __restrict__ td)
{
    int h = blockIdx.x * blockDim.x + threadIdx.x;
    int c = blockIdx.y;
    float w = -expf(td[h]);
    float a = 0.f, b = 0.f, p = -1e30f;
    int t0 = c * CLEN;
    for (int t = t0; t < t0 + CLEN; ++t) {
        int idx = t * HH + h;
        float kk = g_k[idx], vv = g_v[idx];
        float ww = w + p;
        float q = fmaxf(ww, kk);
        float e1 = __expf(ww - q);
        float e2 = __expf(kk - q);
        a = e1 * a + e2 * vv;
        b = e1 * b + e2;
        p = q;
    }
    g_Sa[c * HH + h] = a;
    g_Sb[c * HH + h] = b;
    g_Sm[c * HH + h] = p;
}

__global__ void scan_phaseB(const float* __restrict__ td,
                            const float* __restrict__ aa0, const float* __restrict__ bb0,
                            const float* __restrict__ pp0, const float* __restrict__ hidden,
                            float* __restrict__ out)
{
    int h = blockIdx.x * blockDim.x + threadIdx.x;
    float w = -expf(td[h]);
    float wL = w * (float)CLEN;
    float a = aa0[h], b = bb0[h], p = pp0[h];
    for (int c = 0; c < NCHUNK; ++c) {
        g_Pa[c * HH + h] = a;
        g_Pb[c * HH + h] = b;
        g_Pp[c * HH + h] = p;
        float m = g_Sm[c * HH + h];
        float pd = p + wL;
        float q = fmaxf(pd, m);
        float e1 = __expf(pd - q);
        float e2 = __expf(m - q);
        a = e1 * a + e2 * g_Sa[c * HH + h];
        b = e1 * b + e2 * g_Sb[c * HH + h];
        p = q;
    }
    out[TT * HH + h] = hidden[(TT - 1) * HH + h];
    out[TT * HH + HH + h] = a;
    out[TT * HH + 2 * HH + h] = b;
    out[TT * HH + 3 * HH + h] = p;
}

__global__ void scan_phaseC(const float* __restrict__ td, const float* __restrict__ tf)
{
    int h = blockIdx.x * blockDim.x + threadIdx.x;
    int c = blockIdx.y;
    float w = -expf(td[h]);
    float u = tf[h];
    float a = g_Pa[c * HH + h], b = g_Pb[c * HH + h], p = g_Pp[c * HH + h];
    int t0 = c * CLEN;
    for (int t = t0; t < t0 + CLEN; ++t) {
        int idx = t * HH + h;
        float kk = g_k[idx], vv = g_v[idx];
        float ww = u + kk;
        float q = fmaxf(p, ww);
        float e1 = __expf(p - q);
        float e2 = __expf(ww - q);
        float wkv = (e1 * a + e2 * vv) / (e1 * b + e2);
        float rw = g_r[idx] * wkv;
        __nv_bfloat16 hi, lo;
        split1(rw, hi, lo);
        g_rwh[idx] = hi;
        g_rwl[idx] = lo;
        float ww2 = w + p;
        float q2 = fmaxf(ww2, kk);
        float f1 = __expf(ww2 - q2);
        float f2 = __expf(kk - q2);
        a = f1 * a + f2 * vv;
        b = f1 * b + f2;
        p = q2;
    }
}

extern "C" void kernel_launch(void* const* d_in, const int* in_sizes, int n_in,
                              void* d_out, int out_size)
{
    const float* hidden = (const float*)d_in[0];
    const float* sx     = (const float*)d_in[1];
    const float* aa     = (const float*)d_in[2];
    const float* bb     = (const float*)d_in[3];
    const float* pp     = (const float*)d_in[4];
    const float* td     = (const float*)d_in[5];
    const float* tf     = (const float*)d_in[6];
    const float* tmk    = (const float*)d_in[7];
    const float* tmv    = (const float*)d_in[8];
    const float* tmr    = (const float*)d_in[9];
    const float* Wk     = (const float*)d_in[10];
    const float* Wv     = (const float*)d_in[11];
    const float* Wr     = (const float*)d_in[12];
    const float* Wo     = (const float*)d_in[13];
    float* out = (float*)d_out;

    cudaFuncSetAttribute(mmagemm<0>, cudaFuncAttributeMaxDynamicSharedMemorySize, GSMEM);
    cudaFuncSetAttribute(mmagemm<1>, cudaFuncAttributeMaxDynamicSharedMemorySize, GSMEM);
    cudaFuncSetAttribute(mmagemm<2>, cudaFuncAttributeMaxDynamicSharedMemorySize, GSMEM);

    float *pk, *pv, *pr;
    cudaGetSymbolAddress((void**)&pk, g_k);
    cudaGetSymbolAddress((void**)&pv, g_v);
    cudaGetSymbolAddress((void**)&pr, g_r);
    __nv_bfloat16 *axh, *axl, *wh, *wl, *rwh, *rwl;
    cudaGetSymbolAddress((void**)&axh, g_axh);
    cudaGetSymbolAddress((void**)&axl, g_axl);
    cudaGetSymbolAddress((void**)&wh, g_wh);
    cudaGetSymbolAddress((void**)&wl, g_wl);
    cudaGetSymbolAddress((void**)&rwh, g_rwh);
    cudaGetSymbolAddress((void**)&rwl, g_rwl);
    const size_t AS = (size_t)TT * HH;
    const size_t WS = (size_t)HH * HH;

    dim3 wgrid(HH / 32, HH / 32), wblk(32, 8);
    wsplit<<<wgrid, wblk>>>(Wk, wh + 0 * WS, wl + 0 * WS);
    wsplit<<<wgrid, wblk>>>(Wv, wh + 1 * WS, wl + 1 * WS);
    wsplit<<<wgrid, wblk>>>(Wr, wh + 2 * WS, wl + 2 * WS);
    wsplit<<<wgrid, wblk>>>(Wo, wh + 3 * WS, wl + 3 * WS);
    split_acts<<<(TT * HH / 4) / 256, 256>>>(hidden, sx, tmk, tmv, tmr);

    dim3 gg(HH / BN, TT / BM);
    mmagemm<0><<<gg, 256, GSMEM>>>(axh + 0 * AS, axl + 0 * AS, wh + 0 * WS, wl + 0 * WS, nullptr, pk);
    mmagemm<0><<<gg, 256, GSMEM>>>(axh + 1 * AS, axl + 1 * AS, wh + 1 * WS, wl + 1 * WS, nullptr, pv);
    mmagemm<1><<<gg, 256, GSMEM>>>(axh + 2 * AS, axl + 2 * AS, wh + 2 * WS, wl + 2 * WS, nullptr, pr);

    dim3 sgrid(HH / 256, NCHUNK);
    scan_phaseA<<<sgrid, 256>>>(td);
    scan_phaseB<<<HH / 256, 256>>>(td, aa, bb, pp, hidden, out);
    scan_phaseC<<<sgrid, 256>>>(td, tf);

    mmagemm<2><<<gg, 256, GSMEM>>>(rwh, rwl, wh + 3 * WS, wl + 3 * WS, hidden, out);
}

// round 5
// speedup vs baseline: 3.3245x; 1.4898x over previous
#include <cuda_runtime.h>
#include <cuda_fp16.h>
#include <math.h>
#include <cstdint>

#define TT 8192
#define HH 2048
#define NCHUNK 64
#define CLEN 128

// GEMM tiling
#define BM 128
#define BN 128
#define BKE 32               // K elements per stage (fp16)
#define LDA 40               // row stride in elements (pad 8 -> 80B, conflict-free ldmatrix)
#define TILE_ELEMS (128 * LDA)
#define STAGE_BYTES (2 * TILE_ELEMS * 2)   // A tile + B tile, fp16
#define NSTAGE 4
#define GSMEM (NSTAGE * STAGE_BYTES)       // 81920
#define KITER (2 * HH / BKE)               // 128 (2 split phases x 64)

// ---------------- scratch (device globals; allocation-free) ----------------
__device__ float g_k[TT * HH];
__device__ float g_v[TT * HH];
__device__ float g_r[TT * HH];
__device__ __half g_axh[3][TT * HH];  // mixed activations hi (k,v,r)
__device__ __half g_axl[3][TT * HH];  // lo
__device__ __half g_wt[4][HH * HH];   // W^T fp16 (k,v,r,o)
__device__ __half g_rwh[TT * HH];     // r*wkv hi
__device__ __half g_rwl[TT * HH];     // lo
__device__ float g_Sa[NCHUNK * HH];
__device__ float g_Sb[NCHUNK * HH];
__device__ float g_Sm[NCHUNK * HH];
__device__ float g_Pa[NCHUNK * HH];
__device__ float g_Pb[NCHUNK * HH];
__device__ float g_Pp[NCHUNK * HH];

// ---------------- PTX helpers (plain sm_80-era: work on sm_103 target) ----------------
__device__ __forceinline__ uint32_t smem_u32(const void* p) {
    uint32_t a;
    asm("{ .reg .u64 t; cvta.to.shared.u64 t, %1; cvt.u32.u64 %0, t; }" : "=r"(a) : "l"(p));
    return a;
}

#define CP_ASYNC16(dst, src) \
    asm volatile("cp.async.cg.shared.global [%0], [%1], 16;" :: "r"(dst), "l"(src))
#define CP_COMMIT() asm volatile("cp.async.commit_group;" ::: "memory")
#define CP_WAIT2() asm volatile("cp.async.wait_group 2;" ::: "memory")
#define CP_WAIT0() asm volatile("cp.async.wait_group 0;" ::: "memory")

__device__ __forceinline__ void ldmx4(uint32_t* r, uint32_t addr) {
    asm volatile("ldmatrix.sync.aligned.m8n8.x4.shared.b16 {%0,%1,%2,%3}, [%4];"
                 : "=r"(r[0]), "=r"(r[1]), "=r"(r[2]), "=r"(r[3]) : "r"(addr));
}

__device__ __forceinline__ void mma16816(float* d, const uint32_t* a, uint32_t b0, uint32_t b1) {
    asm volatile("mma.sync.aligned.m16n8k16.row.col.f32.f16.f16.f32 "
                 "{%0,%1,%2,%3}, {%4,%5,%6,%7}, {%8,%9}, {%0,%1,%2,%3};"
                 : "+f"(d[0]), "+f"(d[1]), "+f"(d[2]), "+f"(d[3])
                 : "r"(a[0]), "r"(a[1]), "r"(a[2]), "r"(a[3]), "r"(b0), "r"(b1));
}

__device__ __forceinline__ void split1h(float x, __half& h, __half& l) {
    h = __float2half_rn(x);
    l = __float2half_rn(x - __half2float(h));
}

// ================= fp16 2-term mma.sync GEMM =================
// out[M,N](f32) = act( A[M,K] @ B[N,K]^T ), A given as hi/lo fp16 pair, B fp16.
// 2 accumulation phases over one K-loop: Ahi*B, Alo*B.
// MODE 0: none; MODE 1: sigmoid; MODE 2: + addv
template <int MODE>
__global__ void __launch_bounds__(256, 1)
mmagemm(const __half* __restrict__ Ahi, const __half* __restrict__ Alo,
        const __half* __restrict__ B,
        const float* __restrict__ addv, float* __restrict__ out)
{
    extern __shared__ __half sm[];
    const uint32_t sbase = smem_u32(sm);
    const int tid = threadIdx.x;
    const int wid = tid >> 5, lid = tid & 31;
    const int row0 = blockIdx.y * BM;
    const int col0 = blockIdx.x * BN;
    const int wm = (wid >> 1) * 32;   // warp M offset
    const int wn = (wid & 1) * 64;    // warp N offset

    // per-thread cp.async coordinates: 512 16B-chunks per tile, 2 per thread per tile
    const int r0c = tid >> 2;            // rows tid/4 and tid/4+64
    const int c16 = tid & 3;             // 16B chunk within row (8 elements)

    // ldmatrix lane addressing
    const int lrow = lid & 15;
    const int khalf = (lid >> 4) * 8;

    float acc[2][8][4];
#pragma unroll
    for (int mi = 0; mi < 2; ++mi)
#pragma unroll
        for (int ni = 0; ni < 8; ++ni)
#pragma unroll
            for (int j = 0; j < 4; ++j) acc[mi][ni][j] = 0.f;

    auto load_stage = [&](int buf, int it) {
        const int phase = it >> 6;            // 0,1
        const int kt = (it & 63) * BKE;
        const __half* As = phase ? Alo : Ahi;
        const uint32_t sA = sbase + buf * STAGE_BYTES;
        const uint32_t sB = sA + TILE_ELEMS * 2;
#pragma unroll
        for (int i = 0; i < 2; ++i) {
            const int r = r0c + i * 64;
            const uint32_t so = (r * LDA + c16 * 8) * 2;
            CP_ASYNC16(sA + so, As + (size_t)(row0 + r) * HH + kt + c16 * 8);
            CP_ASYNC16(sB + so, B + (size_t)(col0 + r) * HH + kt + c16 * 8);
        }
        CP_COMMIT();
    };

    load_stage(0, 0);
    load_stage(1, 1);
    load_stage(2, 2);

    for (int it = 0; it < KITER; ++it) {
        CP_WAIT2();
        __syncthreads();
        if (it + 3 < KITER) load_stage((it + 3) & 3, it + 3);

        const uint32_t sA = sbase + (it & 3) * STAGE_BYTES;
        const uint32_t sB = sA + TILE_ELEMS * 2;
#pragma unroll
        for (int k16 = 0; k16 < 2; ++k16) {
            uint32_t a[2][4], b[4][4];
#pragma unroll
            for (int mi = 0; mi < 2; ++mi)
                ldmx4(a[mi], sA + ((wm + 16 * mi + lrow) * LDA + k16 * 16 + khalf) * 2);
#pragma unroll
            for (int nt = 0; nt < 4; ++nt)
                ldmx4(b[nt], sB + ((wn + 16 * nt + lrow) * LDA + k16 * 16 + khalf) * 2);
#pragma unroll
            for (int mi = 0; mi < 2; ++mi)
#pragma unroll
                for (int nt = 0; nt < 4; ++nt) {
                    mma16816(acc[mi][2 * nt + 0], a[mi], b[nt][0], b[nt][2]);
                    mma16816(acc[mi][2 * nt + 1], a[mi], b[nt][1], b[nt][3]);
                }
        }
    }
    CP_WAIT0();

    // epilogue: direct fp32 stores from accumulator fragments
    const int erow = wm + (lid >> 2);
    const int ecol = wn + (lid & 3) * 2;
#pragma unroll
    for (int mi = 0; mi < 2; ++mi)
#pragma unroll
        for (int ni = 0; ni < 8; ++ni)
#pragma unroll
            for (int h = 0; h < 2; ++h) {
                const int r = row0 + erow + mi * 16 + h * 8;
                const int c = col0 + ecol + ni * 8;
                float2 v;
                v.x = acc[mi][ni][h * 2 + 0];
                v.y = acc[mi][ni][h * 2 + 1];
                if (MODE == 1) {
                    v.x = 1.f / (1.f + __expf(-v.x));
                    v.y = 1.f / (1.f + __expf(-v.y));
                }
                const size_t o = (size_t)r * HH + c;
                if (MODE == 2) {
                    float2 hv = *reinterpret_cast<const float2*>(addv + o);
                    v.x += hv.x; v.y += hv.y;
                }
                *reinterpret_cast<float2*>(out + o) = v;
            }
}

// ================= split / transpose prep =================
__global__ void __launch_bounds__(256)
split_acts(const float* __restrict__ hidden, const float* __restrict__ sx,
           const float* __restrict__ tmk, const float* __restrict__ tmv,
           const float* __restrict__ tmr)
{
    const int idx = blockIdx.x * 256 + threadIdx.x;  // float4 index
    const int h4 = idx & (HH / 4 - 1);
    float4 hv = reinterpret_cast<const float4*>(hidden)[idx];
    float4 pv = (idx >= HH / 4) ? reinterpret_cast<const float4*>(hidden)[idx - HH / 4]
                                : reinterpret_cast<const float4*>(sx)[h4];
    const float* tms[3] = {tmk, tmv, tmr};
#pragma unroll
    for (int p = 0; p < 3; ++p) {
        float4 mv = reinterpret_cast<const float4*>(tms[p])[h4];
        union { __half b[4]; uint2 u; } Hh, Ll;
        float x;
        x = fmaf(hv.x - pv.x, mv.x, pv.x); split1h(x, Hh.b[0], Ll.b[0]);
        x = fmaf(hv.y - pv.y, mv.y, pv.y); split1h(x, Hh.b[1], Ll.b[1]);
        x = fmaf(hv.z - pv.z, mv.z, pv.z); split1h(x, Hh.b[2], Ll.b[2]);
        x = fmaf(hv.w - pv.w, mv.w, pv.w); split1h(x, Hh.b[3], Ll.b[3]);
        *reinterpret_cast<uint2*>(&g_axh[p][(size_t)idx * 4]) = Hh.u;
        *reinterpret_cast<uint2*>(&g_axl[p][(size_t)idx * 4]) = Ll.u;
    }
}

// W[K,N] -> W^T[N,K] fp16
__global__ void __launch_bounds__(256)
wtrans(const float* __restrict__ W, __half* __restrict__ T)
{
    __shared__ float ts[32][33];
    const int n0 = blockIdx.x * 32, k0 = blockIdx.y * 32;
    const int tx = threadIdx.x, ty = threadIdx.y;  // 32 x 8
#pragma unroll
    for (int i = 0; i < 4; ++i)
        ts[ty + i * 8][tx] = W[(size_t)(k0 + ty + i * 8) * HH + n0 + tx];
    __syncthreads();
#pragma unroll
    for (int i = 0; i < 4; ++i) {
        const size_t o = (size_t)(n0 + ty + i * 8) * HH + k0 + tx;
        T[o] = __float2half_rn(ts[tx][ty + i * 8]);
    }
}

// ================= WKV chunked scan =================
__global__ void scan_phaseA(const float* __restrict__ td)
{
    int h = blockIdx.x * blockDim.x + threadIdx.x;
    int c = blockIdx.y;
    float w = -expf(td[h]);
    float a = 0.f, b = 0.f, p = -1e30f;
    int t0 = c * CLEN;
    for (int t = t0; t < t0 + CLEN; ++t) {
        int idx = t * HH + h;
        float kk = g_k[idx], vv = g_v[idx];
        float ww = w + p;
        float q = fmaxf(ww, kk);
        float e1 = __expf(ww - q);
        float e2 = __expf(kk - q);
        a = e1 * a + e2 * vv;
        b = e1 * b + e2;
        p = q;
    }
    g_Sa[c * HH + h] = a;
    g_Sb[c * HH + h] = b;
    g_Sm[c * HH + h] = p;
}

__global__ void scan_phaseB(const float* __restrict__ td,
                            const float* __restrict__ aa0, const float* __restrict__ bb0,
                            const float* __restrict__ pp0, const float* __restrict__ hidden,
                            float* __restrict__ out)
{
    int h = blockIdx.x * blockDim.x + threadIdx.x;
    float w = -expf(td[h]);
    float wL = w * (float)CLEN;
    float a = aa0[h], b = bb0[h], p = pp0[h];
    for (int c = 0; c < NCHUNK; ++c) {
        g_Pa[c * HH + h] = a;
        g_Pb[c * HH + h] = b;
        g_Pp[c * HH + h] = p;
        float m = g_Sm[c * HH + h];
        float pd = p + wL;
        float q = fmaxf(pd, m);
        float e1 = __expf(pd - q);
        float e2 = __expf(m - q);
        a = e1 * a + e2 * g_Sa[c * HH + h];
        b = e1 * b + e2 * g_Sb[c * HH + h];
        p = q;
    }
    out[TT * HH + h] = hidden[(TT - 1) * HH + h];
    out[TT * HH + HH + h] = a;
    out[TT * HH + 2 * HH + h] = b;
    out[TT * HH + 3 * HH + h] = p;
}

__global__ void scan_phaseC(const float* __restrict__ td, const float* __restrict__ tf)
{
    int h = blockIdx.x * blockDim.x + threadIdx.x;
    int c = blockIdx.y;
    float w = -expf(td[h]);
    float u = tf[h];
    float a = g_Pa[c * HH + h], b = g_Pb[c * HH + h], p = g_Pp[c * HH + h];
    int t0 = c * CLEN;
    for (int t = t0; t < t0 + CLEN; ++t) {
        int idx = t * HH + h;
        float kk = g_k[idx], vv = g_v[idx];
        float ww = u + kk;
        float q = fmaxf(p, ww);
        float e1 = __expf(p - q);
        float e2 = __expf(ww - q);
        float wkv = (e1 * a + e2 * vv) / (e1 * b + e2);
        float rw = g_r[idx] * wkv;
        __half hi, lo;
        split1h(rw, hi, lo);
        g_rwh[idx] = hi;
        g_rwl[idx] = lo;
        float ww2 = w + p;
        float q2 = fmaxf(ww2, kk);
        float f1 = __expf(ww2 - q2);
        float f2 = __expf(kk - q2);
        a = f1 * a + f2 * vv;
        b = f1 * b + f2;
        p = q2;
    }
}

extern "C" void kernel_launch(void* const* d_in, const int* in_sizes, int n_in,
                              void* d_out, int out_size)
{
    const float* hidden = (const float*)d_in[0];
    const float* sx     = (const float*)d_in[1];
    const float* aa     = (const float*)d_in[2];
    const float* bb     = (const float*)d_in[3];
    const float* pp     = (const float*)d_in[4];
    const float* td     = (const float*)d_in[5];
    const float* tf     = (const float*)d_in[6];
    const float* tmk    = (const float*)d_in[7];
    const float* tmv    = (const float*)d_in[8];
    const float* tmr    = (const float*)d_in[9];
    const float* Wk     = (const float*)d_in[10];
    const float* Wv     = (const float*)d_in[11];
    const float* Wr     = (const float*)d_in[12];
    const float* Wo     = (const float*)d_in[13];
    float* out = (float*)d_out;

    cudaFuncSetAttribute(mmagemm<0>, cudaFuncAttributeMaxDynamicSharedMemorySize, GSMEM);
    cudaFuncSetAttribute(mmagemm<1>, cudaFuncAttributeMaxDynamicSharedMemorySize, GSMEM);
    cudaFuncSetAttribute(mmagemm<2>, cudaFuncAttributeMaxDynamicSharedMemorySize, GSMEM);

    float *pk, *pv, *pr;
    cudaGetSymbolAddress((void**)&pk, g_k);
    cudaGetSymbolAddress((void**)&pv, g_v);
    cudaGetSymbolAddress((void**)&pr, g_r);
    __half *axh, *axl, *wt, *rwh, *rwl;
    cudaGetSymbolAddress((void**)&axh, g_axh);
    cudaGetSymbolAddress((void**)&axl, g_axl);
    cudaGetSymbolAddress((void**)&wt, g_wt);
    cudaGetSymbolAddress((void**)&rwh, g_rwh);
    cudaGetSymbolAddress((void**)&rwl, g_rwl);
    const size_t AS = (size_t)TT * HH;
    const size_t WS = (size_t)HH * HH;

    dim3 wgrid(HH / 32, HH / 32), wblk(32, 8);
    wtrans<<<wgrid, wblk>>>(Wk, wt + 0 * WS);
    wtrans<<<wgrid, wblk>>>(Wv, wt + 1 * WS);
    wtrans<<<wgrid, wblk>>>(Wr, wt + 2 * WS);
    wtrans<<<wgrid, wblk>>>(Wo, wt + 3 * WS);
    split_acts<<<(TT * HH / 4) / 256, 256>>>(hidden, sx, tmk, tmv, tmr);

    dim3 gg(HH / BN, TT / BM);
    mmagemm<0><<<gg, 256, GSMEM>>>(axh + 0 * AS, axl + 0 * AS, wt + 0 * WS, nullptr, pk);
    mmagemm<0><<<gg, 256, GSMEM>>>(axh + 1 * AS, axl + 1 * AS, wt + 1 * WS, nullptr, pv);
    mmagemm<1><<<gg, 256, GSMEM>>>(axh + 2 * AS, axl + 2 * AS, wt + 2 * WS, nullptr, pr);

    dim3 sgrid(HH / 256, NCHUNK);
    scan_phaseA<<<sgrid, 256>>>(td);
    scan_phaseB<<<HH / 256, 256>>>(td, aa, bb, pp, hidden, out);
    scan_phaseC<<<sgrid, 256>>>(td, tf);

    mmagemm<2><<<gg, 256, GSMEM>>>(rwh, rwl, wt + 3 * WS, hidden, out);
}

// round 6
// speedup vs baseline: 5.9101x; 1.7777x over previous
#include <cuda_runtime.h>
#include <cuda_fp16.h>
#include <math.h>
#include <cstdint>

#define TT 8192
#define HH 2048
#define NCHUNK 64
#define CLEN 128

// GEMM tiling
#define BM 128
#define BN 128
#define BKE 32               // K elements per stage (fp16)
#define LDA 40               // row stride in elements (pad 8 -> 80B, conflict-free ldmatrix)
#define TILE_ELEMS (128 * LDA)
#define STAGE_BYTES (2 * TILE_ELEMS * 2)   // A tile + B tile, fp16
#define NSTAGE 4
#define GSMEM (NSTAGE * STAGE_BYTES)       // 81920
#define KITER (HH / BKE)                   // 64

// ---------------- scratch (device globals; allocation-free) ----------------
__device__ float g_k[TT * HH];
__device__ float g_v[TT * HH];
__device__ float g_r[TT * HH];
__device__ __half g_ax[3][TT * HH];   // mixed activations fp16 (k,v,r)
__device__ __half g_wt[4][HH * HH];   // W^T fp16 (k,v,r,o)
__device__ __half g_rw[TT * HH];      // r*wkv fp16
__device__ float g_Sa[NCHUNK * HH];
__device__ float g_Sb[NCHUNK * HH];
__device__ float g_Sm[NCHUNK * HH];
__device__ float g_Pa[NCHUNK * HH];
__device__ float g_Pb[NCHUNK * HH];
__device__ float g_Pp[NCHUNK * HH];

// ---------------- PTX helpers (plain sm_80-era: work on sm_103 target) ----------------
__device__ __forceinline__ uint32_t smem_u32(const void* p) {
    uint32_t a;
    asm("{ .reg .u64 t; cvta.to.shared.u64 t, %1; cvt.u32.u64 %0, t; }" : "=r"(a) : "l"(p));
    return a;
}

#define CP_ASYNC16(dst, src) \
    asm volatile("cp.async.cg.shared.global [%0], [%1], 16;" :: "r"(dst), "l"(src))
#define CP_COMMIT() asm volatile("cp.async.commit_group;" ::: "memory")
#define CP_WAIT2() asm volatile("cp.async.wait_group 2;" ::: "memory")
#define CP_WAIT0() asm volatile("cp.async.wait_group 0;" ::: "memory")

__device__ __forceinline__ void ldmx4(uint32_t* r, uint32_t addr) {
    asm volatile("ldmatrix.sync.aligned.m8n8.x4.shared.b16 {%0,%1,%2,%3}, [%4];"
                 : "=r"(r[0]), "=r"(r[1]), "=r"(r[2]), "=r"(r[3]) : "r"(addr));
}

__device__ __forceinline__ void mma16816(float* d, const uint32_t* a, uint32_t b0, uint32_t b1) {
    asm volatile("mma.sync.aligned.m16n8k16.row.col.f32.f16.f16.f32 "
                 "{%0,%1,%2,%3}, {%4,%5,%6,%7}, {%8,%9}, {%0,%1,%2,%3};"
                 : "+f"(d[0]), "+f"(d[1]), "+f"(d[2]), "+f"(d[3])
                 : "r"(a[0]), "r"(a[1]), "r"(a[2]), "r"(a[3]), "r"(b0), "r"(b1));
}

// ================= fp16 mma.sync GEMM =================
// out[M,N](f32) = act( A[M,K] @ B[N,K]^T ), A and B fp16.
// MODE 0: none; MODE 1: sigmoid; MODE 2: + addv
template <int MODE>
__global__ void __launch_bounds__(256, 1)
mmagemm(const __half* __restrict__ A, const __half* __restrict__ B,
        const float* __restrict__ addv, float* __restrict__ out)
{
    extern __shared__ __half sm[];
    const uint32_t sbase = smem_u32(sm);
    const int tid = threadIdx.x;
    const int wid = tid >> 5, lid = tid & 31;
    const int row0 = blockIdx.y * BM;
    const int col0 = blockIdx.x * BN;
    const int wm = (wid >> 1) * 32;   // warp M offset
    const int wn = (wid & 1) * 64;    // warp N offset

    // per-thread cp.async coordinates: 512 16B-chunks per tile, 2 per thread per tile
    const int r0c = tid >> 2;            // rows tid/4 and tid/4+64
    const int c16 = tid & 3;             // 16B chunk within row (8 elements)

    // ldmatrix lane addressing
    const int lrow = lid & 15;
    const int khalf = (lid >> 4) * 8;

    float acc[2][8][4];
#pragma unroll
    for (int mi = 0; mi < 2; ++mi)
#pragma unroll
        for (int ni = 0; ni < 8; ++ni)
#pragma unroll
            for (int j = 0; j < 4; ++j) acc[mi][ni][j] = 0.f;

    auto load_stage = [&](int buf, int it) {
        const int kt = it * BKE;
        const uint32_t sA = sbase + buf * STAGE_BYTES;
        const uint32_t sB = sA + TILE_ELEMS * 2;
#pragma unroll
        for (int i = 0; i < 2; ++i) {
            const int r = r0c + i * 64;
            const uint32_t so = (r * LDA + c16 * 8) * 2;
            CP_ASYNC16(sA + so, A + (size_t)(row0 + r) * HH + kt + c16 * 8);
            CP_ASYNC16(sB + so, B + (size_t)(col0 + r) * HH + kt + c16 * 8);
        }
        CP_COMMIT();
    };

    load_stage(0, 0);
    load_stage(1, 1);
    load_stage(2, 2);

    for (int it = 0; it < KITER; ++it) {
        CP_WAIT2();
        __syncthreads();
        if (it + 3 < KITER) load_stage((it + 3) & 3, it + 3);

        const uint32_t sA = sbase + (it & 3) * STAGE_BYTES;
        const uint32_t sB = sA + TILE_ELEMS * 2;
#pragma unroll
        for (int k16 = 0; k16 < 2; ++k16) {
            uint32_t a[2][4], b[4][4];
#pragma unroll
            for (int mi = 0; mi < 2; ++mi)
                ldmx4(a[mi], sA + ((wm + 16 * mi + lrow) * LDA + k16 * 16 + khalf) * 2);
#pragma unroll
            for (int nt = 0; nt < 4; ++nt)
                ldmx4(b[nt], sB + ((wn + 16 * nt + lrow) * LDA + k16 * 16 + khalf) * 2);
#pragma unroll
            for (int mi = 0; mi < 2; ++mi)
#pragma unroll
                for (int nt = 0; nt < 4; ++nt) {
                    mma16816(acc[mi][2 * nt + 0], a[mi], b[nt][0], b[nt][2]);
                    mma16816(acc[mi][2 * nt + 1], a[mi], b[nt][1], b[nt][3]);
                }
        }
    }
    CP_WAIT0();

    // epilogue: direct fp32 stores from accumulator fragments
    const int erow = wm + (lid >> 2);
    const int ecol = wn + (lid & 3) * 2;
#pragma unroll
    for (int mi = 0; mi < 2; ++mi)
#pragma unroll
        for (int ni = 0; ni < 8; ++ni)
#pragma unroll
            for (int h = 0; h < 2; ++h) {
                const int r = row0 + erow + mi * 16 + h * 8;
                const int c = col0 + ecol + ni * 8;
                float2 v;
                v.x = acc[mi][ni][h * 2 + 0];
                v.y = acc[mi][ni][h * 2 + 1];
                if (MODE == 1) {
                    v.x = 1.f / (1.f + __expf(-v.x));
                    v.y = 1.f / (1.f + __expf(-v.y));
                }
                const size_t o = (size_t)r * HH + c;
                if (MODE == 2) {
                    float2 hv = *reinterpret_cast<const float2*>(addv + o);
                    v.x += hv.x; v.y += hv.y;
                }
                *reinterpret_cast<float2*>(out + o) = v;
            }
}

// ================= split / transpose prep =================
__global__ void __launch_bounds__(256)
split_acts(const float* __restrict__ hidden, const float* __restrict__ sx,
           const float* __restrict__ tmk, const float* __restrict__ tmv,
           const float* __restrict__ tmr)
{
    const int idx = blockIdx.x * 256 + threadIdx.x;  // float4 index
    const int h4 = idx & (HH / 4 - 1);
    float4 hv = reinterpret_cast<const float4*>(hidden)[idx];
    float4 pv = (idx >= HH / 4) ? reinterpret_cast<const float4*>(hidden)[idx - HH / 4]
                                : reinterpret_cast<const float4*>(sx)[h4];
    const float* tms[3] = {tmk, tmv, tmr};
#pragma unroll
    for (int p = 0; p < 3; ++p) {
        float4 mv = reinterpret_cast<const float4*>(tms[p])[h4];
        union { __half b[4]; uint2 u; } Hh;
        Hh.b[0] = __float2half_rn(fmaf(hv.x - pv.x, mv.x, pv.x));
        Hh.b[1] = __float2half_rn(fmaf(hv.y - pv.y, mv.y, pv.y));
        Hh.b[2] = __float2half_rn(fmaf(hv.z - pv.z, mv.z, pv.z));
        Hh.b[3] = __float2half_rn(fmaf(hv.w - pv.w, mv.w, pv.w));
        *reinterpret_cast<uint2*>(&g_ax[p][(size_t)idx * 4]) = Hh.u;
    }
}

// W[K,N] -> W^T[N,K] fp16
__global__ void __launch_bounds__(256)
wtrans(const float* __restrict__ W, __half* __restrict__ T)
{
    __shared__ float ts[32][33];
    const int n0 = blockIdx.x * 32, k0 = blockIdx.y * 32;
    const int tx = threadIdx.x, ty = threadIdx.y;  // 32 x 8
#pragma unroll
    for (int i = 0; i < 4; ++i)
        ts[ty + i * 8][tx] = W[(size_t)(k0 + ty + i * 8) * HH + n0 + tx];
    __syncthreads();
#pragma unroll
    for (int i = 0; i < 4; ++i) {
        const size_t o = (size_t)(n0 + ty + i * 8) * HH + k0 + tx;
        T[o] = __float2half_rn(ts[tx][ty + i * 8]);
    }
}

// ================= WKV chunked scan =================
__global__ void scan_phaseA(const float* __restrict__ td)
{
    int h = blockIdx.x * blockDim.x + threadIdx.x;
    int c = blockIdx.y;
    float w = -expf(td[h]);
    float a = 0.f, b = 0.f, p = -1e30f;
    int t0 = c * CLEN;
    for (int t = t0; t < t0 + CLEN; ++t) {
        int idx = t * HH + h;
        float kk = g_k[idx], vv = g_v[idx];
        float ww = w + p;
        float q = fmaxf(ww, kk);
        float e1 = __expf(ww - q);
        float e2 = __expf(kk - q);
        a = e1 * a + e2 * vv;
        b = e1 * b + e2;
        p = q;
    }
    g_Sa[c * HH + h] = a;
    g_Sb[c * HH + h] = b;
    g_Sm[c * HH + h] = p;
}

__global__ void scan_phaseB(const float* __restrict__ td,
                            const float* __restrict__ aa0, const float* __restrict__ bb0,
                            const float* __restrict__ pp0, const float* __restrict__ hidden,
                            float* __restrict__ out)
{
    int h = blockIdx.x * blockDim.x + threadIdx.x;
    float w = -expf(td[h]);
    float wL = w * (float)CLEN;
    float a = aa0[h], b = bb0[h], p = pp0[h];
    for (int c = 0; c < NCHUNK; ++c) {
        g_Pa[c * HH + h] = a;
        g_Pb[c * HH + h] = b;
        g_Pp[c * HH + h] = p;
        float m = g_Sm[c * HH + h];
        float pd = p + wL;
        float q = fmaxf(pd, m);
        float e1 = __expf(pd - q);
        float e2 = __expf(m - q);
        a = e1 * a + e2 * g_Sa[c * HH + h];
        b = e1 * b + e2 * g_Sb[c * HH + h];
        p = q;
    }
    out[TT * HH + h] = hidden[(TT - 1) * HH + h];
    out[TT * HH + HH + h] = a;
    out[TT * HH + 2 * HH + h] = b;
    out[TT * HH + 3 * HH + h] = p;
}

__global__ void scan_phaseC(const float* __restrict__ td, const float* __restrict__ tf)
{
    int h = blockIdx.x * blockDim.x + threadIdx.x;
    int c = blockIdx.y;
    float w = -expf(td[h]);
    float u = tf[h];
    float a = g_Pa[c * HH + h], b = g_Pb[c * HH + h], p = g_Pp[c * HH + h];
    int t0 = c * CLEN;
    for (int t = t0; t < t0 + CLEN; ++t) {
        int idx = t * HH + h;
        float kk = g_k[idx], vv = g_v[idx];
        float ww = u + kk;
        float q = fmaxf(p, ww);
        float e1 = __expf(p - q);
        float e2 = __expf(ww - q);
        float wkv = (e1 * a + e2 * vv) / (e1 * b + e2);
        g_rw[idx] = __float2half_rn(g_r[idx] * wkv);
        float ww2 = w + p;
        float q2 = fmaxf(ww2, kk);
        float f1 = __expf(ww2 - q2);
        float f2 = __expf(kk - q2);
        a = f1 * a + f2 * vv;
        b = f1 * b + f2;
        p = q2;
    }
}

extern "C" void kernel_launch(void* const* d_in, const int* in_sizes, int n_in,
                              void* d_out, int out_size)
{
    const float* hidden = (const float*)d_in[0];
    const float* sx     = (const float*)d_in[1];
    const float* aa     = (const float*)d_in[2];
    const float* bb     = (const float*)d_in[3];
    const float* pp     = (const float*)d_in[4];
    const float* td     = (const float*)d_in[5];
    const float* tf     = (const float*)d_in[6];
    const float* tmk    = (const float*)d_in[7];
    const float* tmv    = (const float*)d_in[8];
    const float* tmr    = (const float*)d_in[9];
    const float* Wk     = (const float*)d_in[10];
    const float* Wv     = (const float*)d_in[11];
    const float* Wr     = (const float*)d_in[12];
    const float* Wo     = (const float*)d_in[13];
    float* out = (float*)d_out;

    cudaFuncSetAttribute(mmagemm<0>, cudaFuncAttributeMaxDynamicSharedMemorySize, GSMEM);
    cudaFuncSetAttribute(mmagemm<1>, cudaFuncAttributeMaxDynamicSharedMemorySize, GSMEM);
    cudaFuncSetAttribute(mmagemm<2>, cudaFuncAttributeMaxDynamicSharedMemorySize, GSMEM);

    float *pk, *pv, *pr;
    cudaGetSymbolAddress((void**)&pk, g_k);
    cudaGetSymbolAddress((void**)&pv, g_v);
    cudaGetSymbolAddress((void**)&pr, g_r);
    __half *ax, *wt, *rw;
    cudaGetSymbolAddress((void**)&ax, g_ax);
    cudaGetSymbolAddress((void**)&wt, g_wt);
    cudaGetSymbolAddress((void**)&rw, g_rw);
    const size_t AS = (size_t)TT * HH;
    const size_t WS = (size_t)HH * HH;

    dim3 wgrid(HH / 32, HH / 32), wblk(32, 8);
    wtrans<<<wgrid, wblk>>>(Wk, wt + 0 * WS);
    wtrans<<<wgrid, wblk>>>(Wv, wt + 1 * WS);
    wtrans<<<wgrid, wblk>>>(Wr, wt + 2 * WS);
    wtrans<<<wgrid, wblk>>>(Wo, wt + 3 * WS);
    split_acts<<<(TT * HH / 4) / 256, 256>>>(hidden, sx, tmk, tmv, tmr);

    dim3 gg(HH / BN, TT / BM);
    mmagemm<0><<<gg, 256, GSMEM>>>(ax + 0 * AS, wt + 0 * WS, nullptr, pk);
    mmagemm<0><<<gg, 256, GSMEM>>>(ax + 1 * AS, wt + 1 * WS, nullptr, pv);
    mmagemm<1><<<gg, 256, GSMEM>>>(ax + 2 * AS, wt + 2 * WS, nullptr, pr);

    dim3 sgrid(HH / 256, NCHUNK);
    scan_phaseA<<<sgrid, 256>>>(td);
    scan_phaseB<<<HH / 256, 256>>>(td, aa, bb, pp, hidden, out);
    scan_phaseC<<<sgrid, 256>>>(td, tf);

    mmagemm<2><<<gg, 256, GSMEM>>>(rw, wt + 3 * WS, hidden, out);
}

// round 8
// speedup vs baseline: 6.5143x; 1.1022x over previous
#include <cuda_runtime.h>
#include <cuda_fp16.h>
#include <math.h>
#include <cstdint>

#define TT 8192
#define HH 2048
#define NCHUNK 64
#define CLEN 128

// GEMM tiling
#define BM 128
#define BN 128
#define BKE 64               // K elements per stage (fp16)
#define LDA 72               // row stride in elements (pad 8 -> 144B, conflict-free ldmatrix)
#define TILE_ELEMS (128 * LDA)
#define STAGE_BYTES (2 * TILE_ELEMS * 2)   // A tile + B tile, fp16 (36864)
#define NSTAGE 3
#define GSMEM (NSTAGE * STAGE_BYTES)       // 110592
#define KITER (HH / BKE)                   // 32

// ---------------- scratch (device globals; allocation-free) ----------------
__device__ float g_k[TT * HH];
__device__ float g_v[TT * HH];
__device__ float g_r[TT * HH];
__device__ __half g_ax[3][TT * HH];   // mixed activations fp16 (k,v,r)
__device__ __half g_wt[4][HH * HH];   // W^T fp16 (k,v,r,o)
__device__ __half g_rw[TT * HH];      // r*wkv fp16
__device__ float g_Sa[NCHUNK * HH];
__device__ float g_Sb[NCHUNK * HH];
__device__ float g_Sm[NCHUNK * HH];
__device__ float g_Pa[NCHUNK * HH];
__device__ float g_Pb[NCHUNK * HH];
__device__ float g_Pp[NCHUNK * HH];

// ---------------- PTX helpers (plain sm_80-era: work on sm_103 target) ----------------
__device__ __forceinline__ uint32_t smem_u32(const void* p) {
    uint32_t a;
    asm("{ .reg .u64 t; cvta.to.shared.u64 t, %1; cvt.u32.u64 %0, t; }" : "=r"(a) : "l"(p));
    return a;
}

#define CP_ASYNC16(dst, src) \
    asm volatile("cp.async.cg.shared.global [%0], [%1], 16;" :: "r"(dst), "l"(src))
#define CP_COMMIT() asm volatile("cp.async.commit_group;" ::: "memory")
#define CP_WAIT1() asm volatile("cp.async.wait_group 1;" ::: "memory")
#define CP_WAIT0() asm volatile("cp.async.wait_group 0;" ::: "memory")

__device__ __forceinline__ void ldmx4(uint32_t* r, uint32_t addr) {
    asm volatile("ldmatrix.sync.aligned.m8n8.x4.shared.b16 {%0,%1,%2,%3}, [%4];"
                 : "=r"(r[0]), "=r"(r[1]), "=r"(r[2]), "=r"(r[3]) : "r"(addr));
}

__device__ __forceinline__ void mma16816(float* d, const uint32_t* a, uint32_t b0, uint32_t b1) {
    asm volatile("mma.sync.aligned.m16n8k16.row.col.f32.f16.f16.f32 "
                 "{%0,%1,%2,%3}, {%4,%5,%6,%7}, {%8,%9}, {%0,%1,%2,%3};"
                 : "+f"(d[0]), "+f"(d[1]), "+f"(d[2]), "+f"(d[3])
                 : "r"(a[0]), "r"(a[1]), "r"(a[2]), "r"(a[3]), "r"(b0), "r"(b1));
}

// ================= fp16 mma.sync GEMM =================
// out[M,N](f32) = act( A[M,K] @ B[N,K]^T ), A and B fp16.
// MODE 0: none; MODE 1: sigmoid; MODE 2: + addv
template <int MODE>
__global__ void __launch_bounds__(256, 1)
mmagemm(const __half* __restrict__ A, const __half* __restrict__ B,
        const float* __restrict__ addv, float* __restrict__ out)
{
    extern __shared__ __half sm[];
    const uint32_t sbase = smem_u32(sm);
    const int tid = threadIdx.x;
    const int wid = tid >> 5, lid = tid & 31;
    const int row0 = blockIdx.y * BM;
    const int col0 = blockIdx.x * BN;
    const int wm = (wid >> 1) * 32;   // warp M offset
    const int wn = (wid & 1) * 64;    // warp N offset

    // per-thread cp.async coordinates: 1024 16B-chunks per tile, 4 per thread per tile
    const int r0c = tid >> 3;            // base row (0..31), rows r0c + i*32
    const int c16 = tid & 7;             // 16B chunk within row (8 elements)

    // ldmatrix lane addressing
    const int lrow = lid & 15;
    const int khalf = (lid >> 4) * 8;

    float acc[2][8][4];
#pragma unroll
    for (int mi = 0; mi < 2; ++mi)
#pragma unroll
        for (int ni = 0; ni < 8; ++ni)
#pragma unroll
            for (int j = 0; j < 4; ++j) acc[mi][ni][j] = 0.f;

    auto load_stage = [&](int buf, int it) {
        const int kt = it * BKE;
        const uint32_t sA = sbase + buf * STAGE_BYTES;
        const uint32_t sB = sA + TILE_ELEMS * 2;
#pragma unroll
        for (int i = 0; i < 4; ++i) {
            const int r = r0c + i * 32;
            const uint32_t so = (r * LDA + c16 * 8) * 2;
            CP_ASYNC16(sA + so, A + (size_t)(row0 + r) * HH + kt + c16 * 8);
            CP_ASYNC16(sB + so, B + (size_t)(col0 + r) * HH + kt + c16 * 8);
        }
        CP_COMMIT();
    };

    load_stage(0, 0);
    load_stage(1, 1);

    int buf = 0, nb = 2;
    for (int it = 0; it < KITER; ++it) {
        CP_WAIT1();
        __syncthreads();
        if (it + 2 < KITER) load_stage(nb, it + 2);

        const uint32_t sA = sbase + buf * STAGE_BYTES;
        const uint32_t sB = sA + TILE_ELEMS * 2;
#pragma unroll
        for (int k16 = 0; k16 < 4; ++k16) {
            uint32_t a[2][4], b[4][4];
#pragma unroll
            for (int mi = 0; mi < 2; ++mi)
                ldmx4(a[mi], sA + ((wm + 16 * mi + lrow) * LDA + k16 * 16 + khalf) * 2);
#pragma unroll
            for (int nt = 0; nt < 4; ++nt)
                ldmx4(b[nt], sB + ((wn + 16 * nt + lrow) * LDA + k16 * 16 + khalf) * 2);
#pragma unroll
            for (int mi = 0; mi < 2; ++mi)
#pragma unroll
                for (int nt = 0; nt < 4; ++nt) {
                    mma16816(acc[mi][2 * nt + 0], a[mi], b[nt][0], b[nt][2]);
                    mma16816(acc[mi][2 * nt + 1], a[mi], b[nt][1], b[nt][3]);
                }
        }
        buf = (buf + 1 == NSTAGE) ? 0 : buf + 1;
        nb = (nb + 1 == NSTAGE) ? 0 : nb + 1;
    }
    CP_WAIT0();

    // epilogue: direct fp32 stores from accumulator fragments
    const int erow = wm + (lid >> 2);
    const int ecol = wn + (lid & 3) * 2;
#pragma unroll
    for (int mi = 0; mi < 2; ++mi)
#pragma unroll
        for (int ni = 0; ni < 8; ++ni)
#pragma unroll
            for (int h = 0; h < 2; ++h) {
                const int r = row0 + erow + mi * 16 + h * 8;
                const int c = col0 + ecol + ni * 8;
                float2 v;
                v.x = acc[mi][ni][h * 2 + 0];
                v.y = acc[mi][ni][h * 2 + 1];
                if (MODE == 1) {
                    v.x = 1.f / (1.f + __expf(-v.x));
                    v.y = 1.f / (1.f + __expf(-v.y));
                }
                const size_t o = (size_t)r * HH + c;
                if (MODE == 2) {
                    float2 hv = *reinterpret_cast<const float2*>(addv + o);
                    v.x += hv.x; v.y += hv.y;
                }
                *reinterpret_cast<float2*>(out + o) = v;
            }
}

// ================= split / transpose prep =================
__global__ void __launch_bounds__(256)
split_acts(const float* __restrict__ hidden, const float* __restrict__ sx,
           const float* __restrict__ tmk, const float* __restrict__ tmv,
           const float* __restrict__ tmr)
{
    const int idx = blockIdx.x * 256 + threadIdx.x;  // float4 index
    const int h4 = idx & (HH / 4 - 1);
    float4 hv = reinterpret_cast<const float4*>(hidden)[idx];
    float4 pv = (idx >= HH / 4) ? reinterpret_cast<const float4*>(hidden)[idx - HH / 4]
                                : reinterpret_cast<const float4*>(sx)[h4];
    const float* tms[3] = {tmk, tmv, tmr};
#pragma unroll
    for (int p = 0; p < 3; ++p) {
        float4 mv = reinterpret_cast<const float4*>(tms[p])[h4];
        union { __half b[4]; uint2 u; } Hh;
        Hh.b[0] = __float2half_rn(fmaf(hv.x - pv.x, mv.x, pv.x));
        Hh.b[1] = __float2half_rn(fmaf(hv.y - pv.y, mv.y, pv.y));
        Hh.b[2] = __float2half_rn(fmaf(hv.z - pv.z, mv.z, pv.z));
        Hh.b[3] = __float2half_rn(fmaf(hv.w - pv.w, mv.w, pv.w));
        *reinterpret_cast<uint2*>(&g_ax[p][(size_t)idx * 4]) = Hh.u;
    }
}

// W[K,N] -> W^T[N,K] fp16, all 4 weights in one launch (grid.z selects W)
__global__ void __launch_bounds__(256)
wtrans4(const float* __restrict__ W0, const float* __restrict__ W1,
        const float* __restrict__ W2, const float* __restrict__ W3)
{
    __shared__ float ts[32][33];
    const int z = blockIdx.z;
    const float* W = (z == 0) ? W0 : (z == 1) ? W1 : (z == 2) ? W2 : W3;
    __half* T = &g_wt[z][0];
    const int n0 = blockIdx.x * 32, k0 = blockIdx.y * 32;
    const int tx = threadIdx.x, ty = threadIdx.y;  // 32 x 8
#pragma unroll
    for (int i = 0; i < 4; ++i)
        ts[ty + i * 8][tx] = W[(size_t)(k0 + ty + i * 8) * HH + n0 + tx];
    __syncthreads();
#pragma unroll
    for (int i = 0; i < 4; ++i) {
        const size_t o = (size_t)(n0 + ty + i * 8) * HH + k0 + tx;
        T[o] = __float2half_rn(ts[tx][ty + i * 8]);
    }
}

// ================= WKV chunked scan =================
__global__ void scan_phaseA(const float* __restrict__ td)
{
    int h = blockIdx.x * blockDim.x + threadIdx.x;
    int c = blockIdx.y;
    float w = -expf(td[h]);
    float a = 0.f, b = 0.f, p = -1e30f;
    int t0 = c * CLEN;
    for (int t = t0; t < t0 + CLEN; ++t) {
        int idx = t * HH + h;
        float kk = g_k[idx], vv = g_v[idx];
        float ww = w + p;
        float q = fmaxf(ww, kk);
        float e1 = __expf(ww - q);
        float e2 = __expf(kk - q);
        a = e1 * a + e2 * vv;
        b = e1 * b + e2;
        p = q;
    }
    g_Sa[c * HH + h] = a;
    g_Sb[c * HH + h] = b;
    g_Sm[c * HH + h] = p;
}

__global__ void scan_phaseB(const float* __restrict__ td,
                            const float* __restrict__ aa0, const float* __restrict__ bb0,
                            const float* __restrict__ pp0, const float* __restrict__ hidden,
                            float* __restrict__ out)
{
    int h = blockIdx.x * blockDim.x + threadIdx.x;
    float w = -expf(td[h]);
    float wL = w * (float)CLEN;
    float a = aa0[h], b = bb0[h], p = pp0[h];
    for (int c = 0; c < NCHUNK; ++c) {
        g_Pa[c * HH + h] = a;
        g_Pb[c * HH + h] = b;
        g_Pp[c * HH + h] = p;
        float m = g_Sm[c * HH + h];
        float pd = p + wL;
        float q = fmaxf(pd, m);
        float e1 = __expf(pd - q);
        float e2 = __expf(m - q);
        a = e1 * a + e2 * g_Sa[c * HH + h];
        b = e1 * b + e2 * g_Sb[c * HH + h];
        p = q;
    }
    out[TT * HH + h] = hidden[(TT - 1) * HH + h];
    out[TT * HH + HH + h] = a;
    out[TT * HH + 2 * HH + h] = b;
    out[TT * HH + 3 * HH + h] = p;
}

__global__ void scan_phaseC(const float* __restrict__ td, const float* __restrict__ tf)
{
    int h = blockIdx.x * blockDim.x + threadIdx.x;
    int c = blockIdx.y;
    float w = -expf(td[h]);
    float u = tf[h];
    float a = g_Pa[c * HH + h], b = g_Pb[c * HH + h], p = g_Pp[c * HH + h];
    int t0 = c * CLEN;
    for (int t = t0; t < t0 + CLEN; ++t) {
        int idx = t * HH + h;
        float kk = g_k[idx], vv = g_v[idx];
        float ww = u + kk;
        float q = fmaxf(p, ww);
        float e1 = __expf(p - q);
        float e2 = __expf(ww - q);
        float wkv = (e1 * a + e2 * vv) / (e1 * b + e2);
        g_rw[idx] = __float2half_rn(g_r[idx] * wkv);
        float ww2 = w + p;
        float q2 = fmaxf(ww2, kk);
        float f1 = __expf(ww2 - q2);
        float f2 = __expf(kk - q2);
        a = f1 * a + f2 * vv;
        b = f1 * b + f2;
        p = q2;
    }
}

extern "C" void kernel_launch(void* const* d_in, const int* in_sizes, int n_in,
                              void* d_out, int out_size)
{
    const float* hidden = (const float*)d_in[0];
    const float* sx     = (const float*)d_in[1];
    const float* aa     = (const float*)d_in[2];
    const float* bb     = (const float*)d_in[3];
    const float* pp     = (const float*)d_in[4];
    const float* td     = (const float*)d_in[5];
    const float* tf     = (const float*)d_in[6];
    const float* tmk    = (const float*)d_in[7];
    const float* tmv    = (const float*)d_in[8];
    const float* tmr    = (const float*)d_in[9];
    const float* Wk     = (const float*)d_in[10];
    const float* Wv     = (const float*)d_in[11];
    const float* Wr     = (const float*)d_in[12];
    const float* Wo     = (const float*)d_in[13];
    float* out = (float*)d_out;

    cudaFuncSetAttribute(mmagemm<0>, cudaFuncAttributeMaxDynamicSharedMemorySize, GSMEM);
    cudaFuncSetAttribute(mmagemm<1>, cudaFuncAttributeMaxDynamicSharedMemorySize, GSMEM);
    cudaFuncSetAttribute(mmagemm<2>, cudaFuncAttributeMaxDynamicSharedMemorySize, GSMEM);

    float *pk, *pv, *pr;
    cudaGetSymbolAddress((void**)&pk, g_k);
    cudaGetSymbolAddress((void**)&pv, g_v);
    cudaGetSymbolAddress((void**)&pr, g_r);
    __half *ax, *wt, *rw;
    cudaGetSymbolAddress((void**)&ax, g_ax);
    cudaGetSymbolAddress((void**)&wt, g_wt);
    cudaGetSymbolAddress((void**)&rw, g_rw);
    const size_t AS = (size_t)TT * HH;
    const size_t WS = (size_t)HH * HH;

    dim3 wgrid(HH / 32, HH / 32, 4), wblk(32, 8);
    wtrans4<<<wgrid, wblk>>>(Wk, Wv, Wr, Wo);
    split_acts<<<(TT * HH / 4) / 256, 256>>>(hidden, sx, tmk, tmv, tmr);

    dim3 gg(HH / BN, TT / BM);
    mmagemm<0><<<gg, 256, GSMEM>>>(ax + 0 * AS, wt + 0 * WS, nullptr, pk);
    mmagemm<0><<<gg, 256, GSMEM>>>(ax + 1 * AS, wt + 1 * WS, nullptr, pv);
    mmagemm<1><<<gg, 256, GSMEM>>>(ax + 2 * AS, wt + 2 * WS, nullptr, pr);

    dim3 sgrid(HH / 256, NCHUNK);
    scan_phaseA<<<sgrid, 256>>>(td);
    scan_phaseB<<<HH / 256, 256>>>(td, aa, bb, pp, hidden, out);
    scan_phaseC<<<sgrid, 256>>>(td, tf);

    mmagemm<2><<<gg, 256, GSMEM>>>(rw, wt + 3 * WS, hidden, out);
}

// round 9
// speedup vs baseline: 6.7000x; 1.0285x over previous
#include <cuda_runtime.h>
#include <cuda_fp16.h>
#include <math.h>
#include <cstdint>

#define TT 8192
#define HH 2048
#define NCHUNK 64
#define CLEN 128

// GEMM tiling
#define BM 128
#define BN 128
#define BKE 64               // K elements per stage (fp16)
#define LDA 72               // row stride in elements (pad 8 -> 144B, conflict-free ldmatrix)
#define TILE_ELEMS (128 * LDA)
#define STAGE_BYTES (2 * TILE_ELEMS * 2)   // A tile + B tile, fp16 (36864)
#define NSTAGE 3
#define GSMEM (NSTAGE * STAGE_BYTES)       // 110592 -> 2 CTAs/SM = 221184 <= 228KB
#define KITER (HH / BKE)                   // 32

// ---------------- scratch (device globals; allocation-free) ----------------
__device__ float g_k[TT * HH];
__device__ float g_v[TT * HH];
__device__ float g_r[TT * HH];
__device__ __half g_ax[3][TT * HH];   // mixed activations fp16 (k,v,r)
__device__ __half g_wt[4][HH * HH];   // W^T fp16 (k,v,r,o)
__device__ __half g_rw[TT * HH];      // r*wkv fp16
__device__ float g_Sa[NCHUNK * HH];
__device__ float g_Sb[NCHUNK * HH];
__device__ float g_Sm[NCHUNK * HH];
__device__ float g_Pa[NCHUNK * HH];
__device__ float g_Pb[NCHUNK * HH];
__device__ float g_Pp[NCHUNK * HH];

// ---------------- PTX helpers (plain sm_80-era: work on sm_103 target) ----------------
__device__ __forceinline__ uint32_t smem_u32(const void* p) {
    uint32_t a;
    asm("{ .reg .u64 t; cvta.to.shared.u64 t, %1; cvt.u32.u64 %0, t; }" : "=r"(a) : "l"(p));
    return a;
}

#define CP_ASYNC16(dst, src) \
    asm volatile("cp.async.cg.shared.global [%0], [%1], 16;" :: "r"(dst), "l"(src))
#define CP_COMMIT() asm volatile("cp.async.commit_group;" ::: "memory")
#define CP_WAIT1() asm volatile("cp.async.wait_group 1;" ::: "memory")
#define CP_WAIT0() asm volatile("cp.async.wait_group 0;" ::: "memory")

__device__ __forceinline__ void ldmx4(uint32_t* r, uint32_t addr) {
    asm volatile("ldmatrix.sync.aligned.m8n8.x4.shared.b16 {%0,%1,%2,%3}, [%4];"
                 : "=r"(r[0]), "=r"(r[1]), "=r"(r[2]), "=r"(r[3]) : "r"(addr));
}

__device__ __forceinline__ void mma16816(float* d, const uint32_t* a, uint32_t b0, uint32_t b1) {
    asm volatile("mma.sync.aligned.m16n8k16.row.col.f32.f16.f16.f32 "
                 "{%0,%1,%2,%3}, {%4,%5,%6,%7}, {%8,%9}, {%0,%1,%2,%3};"
                 : "+f"(d[0]), "+f"(d[1]), "+f"(d[2]), "+f"(d[3])
                 : "r"(a[0]), "r"(a[1]), "r"(a[2]), "r"(a[3]), "r"(b0), "r"(b1));
}

// ================= fp16 mma.sync GEMM =================
// out[M,N](f32) = act( A[M,K] @ B[N,K]^T ), A and B fp16.
// MODE 0: none; MODE 1: sigmoid; MODE 2: + addv
template <int MODE>
__global__ void __launch_bounds__(256, 2)
mmagemm(const __half* __restrict__ A, const __half* __restrict__ B,
        const float* __restrict__ addv, float* __restrict__ out)
{
    extern __shared__ __half sm[];
    const uint32_t sbase = smem_u32(sm);
    const int tid = threadIdx.x;
    const int wid = tid >> 5, lid = tid & 31;
    const int row0 = blockIdx.y * BM;
    const int col0 = blockIdx.x * BN;
    const int wm = (wid >> 1) * 32;   // warp M offset
    const int wn = (wid & 1) * 64;    // warp N offset

    // per-thread cp.async coordinates: 1024 16B-chunks per tile, 4 per thread per tile
    const int r0c = tid >> 3;            // base row (0..31), rows r0c + i*32
    const int c16 = tid & 7;             // 16B chunk within row (8 elements)

    // ldmatrix lane addressing
    const int lrow = lid & 15;
    const int khalf = (lid >> 4) * 8;

    float acc[2][8][4];
#pragma unroll
    for (int mi = 0; mi < 2; ++mi)
#pragma unroll
        for (int ni = 0; ni < 8; ++ni)
#pragma unroll
            for (int j = 0; j < 4; ++j) acc[mi][ni][j] = 0.f;

    auto load_stage = [&](int buf, int it) {
        const int kt = it * BKE;
        const uint32_t sA = sbase + buf * STAGE_BYTES;
        const uint32_t sB = sA + TILE_ELEMS * 2;
#pragma unroll
        for (int i = 0; i < 4; ++i) {
            const int r = r0c + i * 32;
            const uint32_t so = (r * LDA + c16 * 8) * 2;
            CP_ASYNC16(sA + so, A + (size_t)(row0 + r) * HH + kt + c16 * 8);
            CP_ASYNC16(sB + so, B + (size_t)(col0 + r) * HH + kt + c16 * 8);
        }
        CP_COMMIT();
    };

    load_stage(0, 0);
    load_stage(1, 1);

    int buf = 0, nb = 2;
    for (int it = 0; it < KITER; ++it) {
        CP_WAIT1();
        __syncthreads();
        if (it + 2 < KITER) load_stage(nb, it + 2);

        const uint32_t sA = sbase + buf * STAGE_BYTES;
        const uint32_t sB = sA + TILE_ELEMS * 2;
#pragma unroll
        for (int k16 = 0; k16 < 4; ++k16) {
            uint32_t a[2][4], b[4][4];
#pragma unroll
            for (int mi = 0; mi < 2; ++mi)
                ldmx4(a[mi], sA + ((wm + 16 * mi + lrow) * LDA + k16 * 16 + khalf) * 2);
#pragma unroll
            for (int nt = 0; nt < 4; ++nt)
                ldmx4(b[nt], sB + ((wn + 16 * nt + lrow) * LDA + k16 * 16 + khalf) * 2);
#pragma unroll
            for (int mi = 0; mi < 2; ++mi)
#pragma unroll
                for (int nt = 0; nt < 4; ++nt) {
                    mma16816(acc[mi][2 * nt + 0], a[mi], b[nt][0], b[nt][2]);
                    mma16816(acc[mi][2 * nt + 1], a[mi], b[nt][1], b[nt][3]);
                }
        }
        buf = (buf + 1 == NSTAGE) ? 0 : buf + 1;
        nb = (nb + 1 == NSTAGE) ? 0 : nb + 1;
    }
    CP_WAIT0();

    // epilogue: direct fp32 stores from accumulator fragments
    const int erow = wm + (lid >> 2);
    const int ecol = wn + (lid & 3) * 2;
#pragma unroll
    for (int mi = 0; mi < 2; ++mi)
#pragma unroll
        for (int ni = 0; ni < 8; ++ni)
#pragma unroll
            for (int h = 0; h < 2; ++h) {
                const int r = row0 + erow + mi * 16 + h * 8;
                const int c = col0 + ecol + ni * 8;
                float2 v;
                v.x = acc[mi][ni][h * 2 + 0];
                v.y = acc[mi][ni][h * 2 + 1];
                if (MODE == 1) {
                    v.x = 1.f / (1.f + __expf(-v.x));
                    v.y = 1.f / (1.f + __expf(-v.y));
                }
                const size_t o = (size_t)r * HH + c;
                if (MODE == 2) {
                    float2 hv = *reinterpret_cast<const float2*>(addv + o);
                    v.x += hv.x; v.y += hv.y;
                }
                *reinterpret_cast<float2*>(out + o) = v;
            }
}

// ================= split / transpose prep =================
__global__ void __launch_bounds__(256)
split_acts(const float* __restrict__ hidden, const float* __restrict__ sx,
           const float* __restrict__ tmk, const float* __restrict__ tmv,
           const float* __restrict__ tmr)
{
    const int idx = blockIdx.x * 256 + threadIdx.x;  // float4 index
    const int h4 = idx & (HH / 4 - 1);
    float4 hv = reinterpret_cast<const float4*>(hidden)[idx];
    float4 pv = (idx >= HH / 4) ? reinterpret_cast<const float4*>(hidden)[idx - HH / 4]
                                : reinterpret_cast<const float4*>(sx)[h4];
    const float* tms[3] = {tmk, tmv, tmr};
#pragma unroll
    for (int p = 0; p < 3; ++p) {
        float4 mv = reinterpret_cast<const float4*>(tms[p])[h4];
        union { __half b[4]; uint2 u; } Hh;
        Hh.b[0] = __float2half_rn(fmaf(hv.x - pv.x, mv.x, pv.x));
        Hh.b[1] = __float2half_rn(fmaf(hv.y - pv.y, mv.y, pv.y));
        Hh.b[2] = __float2half_rn(fmaf(hv.z - pv.z, mv.z, pv.z));
        Hh.b[3] = __float2half_rn(fmaf(hv.w - pv.w, mv.w, pv.w));
        *reinterpret_cast<uint2*>(&g_ax[p][(size_t)idx * 4]) = Hh.u;
    }
}

// W[K,N] -> W^T[N,K] fp16, all 4 weights in one launch (grid.z selects W)
__global__ void __launch_bounds__(256)
wtrans4(const float* __restrict__ W0, const float* __restrict__ W1,
        const float* __restrict__ W2, const float* __restrict__ W3)
{
    __shared__ float ts[32][33];
    const int z = blockIdx.z;
    const float* W = (z == 0) ? W0 : (z == 1) ? W1 : (z == 2) ? W2 : W3;
    __half* T = &g_wt[z][0];
    const int n0 = blockIdx.x * 32, k0 = blockIdx.y * 32;
    const int tx = threadIdx.x, ty = threadIdx.y;  // 32 x 8
#pragma unroll
    for (int i = 0; i < 4; ++i)
        ts[ty + i * 8][tx] = W[(size_t)(k0 + ty + i * 8) * HH + n0 + tx];
    __syncthreads();
#pragma unroll
    for (int i = 0; i < 4; ++i) {
        const size_t o = (size_t)(n0 + ty + i * 8) * HH + k0 + tx;
        T[o] = __float2half_rn(ts[tx][ty + i * 8]);
    }
}

// ================= WKV chunked scan =================
__global__ void scan_phaseA(const float* __restrict__ td)
{
    int h = blockIdx.x * blockDim.x + threadIdx.x;
    int c = blockIdx.y;
    float w = -expf(td[h]);
    float a = 0.f, b = 0.f, p = -1e30f;
    int t0 = c * CLEN;
    for (int t = t0; t < t0 + CLEN; ++t) {
        int idx = t * HH + h;
        float kk = g_k[idx], vv = g_v[idx];
        float ww = w + p;
        float q = fmaxf(ww, kk);
        float e1 = __expf(ww - q);
        float e2 = __expf(kk - q);
        a = e1 * a + e2 * vv;
        b = e1 * b + e2;
        p = q;
    }
    g_Sa[c * HH + h] = a;
    g_Sb[c * HH + h] = b;
    g_Sm[c * HH + h] = p;
}

__global__ void scan_phaseB(const float* __restrict__ td,
                            const float* __restrict__ aa0, const float* __restrict__ bb0,
                            const float* __restrict__ pp0, const float* __restrict__ hidden,
                            float* __restrict__ out)
{
    int h = blockIdx.x * blockDim.x + threadIdx.x;
    float w = -expf(td[h]);
    float wL = w * (float)CLEN;
    float a = aa0[h], b = bb0[h], p = pp0[h];
    for (int c = 0; c < NCHUNK; ++c) {
        g_Pa[c * HH + h] = a;
        g_Pb[c * HH + h] = b;
        g_Pp[c * HH + h] = p;
        float m = g_Sm[c * HH + h];
        float pd = p + wL;
        float q = fmaxf(pd, m);
        float e1 = __expf(pd - q);
        float e2 = __expf(m - q);
        a = e1 * a + e2 * g_Sa[c * HH + h];
        b = e1 * b + e2 * g_Sb[c * HH + h];
        p = q;
    }
    out[TT * HH + h] = hidden[(TT - 1) * HH + h];
    out[TT * HH + HH + h] = a;
    out[TT * HH + 2 * HH + h] = b;
    out[TT * HH + 3 * HH + h] = p;
}

__global__ void scan_phaseC(const float* __restrict__ td, const float* __restrict__ tf)
{
    int h = blockIdx.x * blockDim.x + threadIdx.x;
    int c = blockIdx.y;
    float w = -expf(td[h]);
    float u = tf[h];
    float a = g_Pa[c * HH + h], b = g_Pb[c * HH + h], p = g_Pp[c * HH + h];
    int t0 = c * CLEN;
    for (int t = t0; t < t0 + CLEN; ++t) {
        int idx = t * HH + h;
        float kk = g_k[idx], vv = g_v[idx];
        float ww = u + kk;
        float q = fmaxf(p, ww);
        float e1 = __expf(p - q);
        float e2 = __expf(ww - q);
        float wkv = (e1 * a + e2 * vv) / (e1 * b + e2);
        g_rw[idx] = __float2half_rn(g_r[idx] * wkv);
        float ww2 = w + p;
        float q2 = fmaxf(ww2, kk);
        float f1 = __expf(ww2 - q2);
        float f2 = __expf(kk - q2);
        a = f1 * a + f2 * vv;
        b = f1 * b + f2;
        p = q2;
    }
}

extern "C" void kernel_launch(void* const* d_in, const int* in_sizes, int n_in,
                              void* d_out, int out_size)
{
    const float* hidden = (const float*)d_in[0];
    const float* sx     = (const float*)d_in[1];
    const float* aa     = (const float*)d_in[2];
    const float* bb     = (const float*)d_in[3];
    const float* pp     = (const float*)d_in[4];
    const float* td     = (const float*)d_in[5];
    const float* tf     = (const float*)d_in[6];
    const float* tmk    = (const float*)d_in[7];
    const float* tmv    = (const float*)d_in[8];
    const float* tmr    = (const float*)d_in[9];
    const float* Wk     = (const float*)d_in[10];
    const float* Wv     = (const float*)d_in[11];
    const float* Wr     = (const float*)d_in[12];
    const float* Wo     = (const float*)d_in[13];
    float* out = (float*)d_out;

    cudaFuncSetAttribute(mmagemm<0>, cudaFuncAttributeMaxDynamicSharedMemorySize, GSMEM);
    cudaFuncSetAttribute(mmagemm<1>, cudaFuncAttributeMaxDynamicSharedMemorySize, GSMEM);
    cudaFuncSetAttribute(mmagemm<2>, cudaFuncAttributeMaxDynamicSharedMemorySize, GSMEM);

    float *pk, *pv, *pr;
    cudaGetSymbolAddress((void**)&pk, g_k);
    cudaGetSymbolAddress((void**)&pv, g_v);
    cudaGetSymbolAddress((void**)&pr, g_r);
    __half *ax, *wt, *rw;
    cudaGetSymbolAddress((void**)&ax, g_ax);
    cudaGetSymbolAddress((void**)&wt, g_wt);
    cudaGetSymbolAddress((void**)&rw, g_rw);
    const size_t AS = (size_t)TT * HH;
    const size_t WS = (size_t)HH * HH;

    dim3 wgrid(HH / 32, HH / 32, 4), wblk(32, 8);
    wtrans4<<<wgrid, wblk>>>(Wk, Wv, Wr, Wo);
    split_acts<<<(TT * HH / 4) / 256, 256>>>(hidden, sx, tmk, tmv, tmr);

    dim3 gg(HH / BN, TT / BM);
    mmagemm<0><<<gg, 256, GSMEM>>>(ax + 0 * AS, wt + 0 * WS, nullptr, pk);
    mmagemm<0><<<gg, 256, GSMEM>>>(ax + 1 * AS, wt + 1 * WS, nullptr, pv);
    mmagemm<1><<<gg, 256, GSMEM>>>(ax + 2 * AS, wt + 2 * WS, nullptr, pr);

    dim3 sgrid(HH / 256, NCHUNK);
    scan_phaseA<<<sgrid, 256>>>(td);
    scan_phaseB<<<HH / 256, 256>>>(td, aa, bb, pp, hidden, out);
    scan_phaseC<<<sgrid, 256>>>(td, tf);

    mmagemm<2><<<gg, 256, GSMEM>>>(rw, wt + 3 * WS, hidden, out);
}